// round 11
// baseline (speedup 1.0000x reference)
#include <cuda_runtime.h>
#include <math.h>

// Problem dims (fixed by the reference setup_inputs)
#define BSZ    8192
#define DDIM   1024
#define D2     512
#define NH     2048
#define FSTEPS 8

// Scratch (allocation-free rule: __device__ globals)
__device__ float  g_h1[(size_t)BSZ * NH];   // 64 MB
__device__ float  g_h2[(size_t)BSZ * NH];   // 64 MB
__device__ float  g_z0[(size_t)BSZ * DDIM]; // 32 MB
__device__ float  g_z1[(size_t)BSZ * DDIM]; // 32 MB
__device__ double g_partial[1024];

__device__ __forceinline__ float lrelu(float x) {
    // jax.nn.leaky_relu default slope 0.01
    return fmaxf(x, 0.01f * x);
}

__device__ __forceinline__ float logsigf(float x) {
    // matches jax: min(x,0) - log1p(exp(-|x|))
    if (x >= 0.0f) return -log1pf(expf(-x));
    return x - log1pf(expf(x));
}

// ---------------------------------------------------------------------------
// SGEMM: C(M=8192 x Nn) = A(M x K, row stride lda) * Bw(K x Nn, row-major)
// EPI==0: C[r][n] = lrelu(acc + bias[n])
// EPI==1: coupling epilogue:
//   t  = acc + bias[n]                  (n in [0, 512))
//   yb = Zin[r][512+n] + rint(t)
//   Zout[r][511-n]  = yb                (reversed concat)
//   Zout[r][1023-n] = Zin[r][n]
// Tiling: 128x128 block, BK=8, 256 threads, 8x8 per thread, double-buffered.
// ---------------------------------------------------------------------------
template <int EPI>
__global__ __launch_bounds__(256)
void sgemm_kernel(const float* __restrict__ A, int lda,
                  const float* __restrict__ Bw,
                  const float* __restrict__ bias,
                  float* __restrict__ C,
                  const float* __restrict__ Zin,
                  float* __restrict__ Zout,
                  int Nn, int K)
{
    const int BM = 128, BN = 128, BK = 8;
    __shared__ float As[2][BK][BM];   // transposed A tile
    __shared__ float Bs[2][BK][BN];

    const int tid = threadIdx.x;
    const int bx = blockIdx.x;  // N tile
    const int by = blockIdx.y;  // M tile

    // global->shared load mapping (one float4 each for A and B per k-tile)
    const int aRow = tid >> 1;           // 0..127
    const int aCol = (tid & 1) << 2;     // 0 or 4  (k offset)
    const int bRow = tid >> 5;           // 0..7    (k offset)
    const int bCol = (tid & 31) << 2;    // 0..124

    const float* Aptr = A  + (size_t)(by * BM + aRow) * lda + aCol;
    const float* Bptr = Bw + (size_t)bRow * Nn + (size_t)bx * BN + bCol;

    // compute mapping: 4+4 split in both dims for conflict-free LDS.128
    const int tr = tid >> 4;   // 0..15
    const int tc = tid & 15;   // 0..15

    float acc[8][8];
#pragma unroll
    for (int i = 0; i < 8; ++i)
#pragma unroll
        for (int j = 0; j < 8; ++j) acc[i][j] = 0.0f;

    // prologue: tile 0 into buf 0
    {
        float4 a4 = *(const float4*)Aptr;
        As[0][aCol + 0][aRow] = a4.x;
        As[0][aCol + 1][aRow] = a4.y;
        As[0][aCol + 2][aRow] = a4.z;
        As[0][aCol + 3][aRow] = a4.w;
        float4 b4 = *(const float4*)Bptr;
        *(float4*)&Bs[0][bRow][bCol] = b4;
    }
    __syncthreads();

    const int KT = K / BK;
    int buf = 0;

    for (int kt = 0; kt < KT; ++kt) {
        float4 na, nb;
        if (kt + 1 < KT) {
            na = *(const float4*)(Aptr + (kt + 1) * BK);
            nb = *(const float4*)(Bptr + (size_t)(kt + 1) * BK * Nn);
        }

#pragma unroll
        for (int k = 0; k < BK; ++k) {
            float4 a0 = *(const float4*)&As[buf][k][tr * 4];
            float4 a1 = *(const float4*)&As[buf][k][64 + tr * 4];
            float4 b0 = *(const float4*)&Bs[buf][k][tc * 4];
            float4 b1 = *(const float4*)&Bs[buf][k][64 + tc * 4];
            float rm[8] = {a0.x, a0.y, a0.z, a0.w, a1.x, a1.y, a1.z, a1.w};
            float rn[8] = {b0.x, b0.y, b0.z, b0.w, b1.x, b1.y, b1.z, b1.w};
#pragma unroll
            for (int i = 0; i < 8; ++i)
#pragma unroll
                for (int j = 0; j < 8; ++j)
                    acc[i][j] = fmaf(rm[i], rn[j], acc[i][j]);
        }

        if (kt + 1 < KT) {
            As[buf ^ 1][aCol + 0][aRow] = na.x;
            As[buf ^ 1][aCol + 1][aRow] = na.y;
            As[buf ^ 1][aCol + 2][aRow] = na.z;
            As[buf ^ 1][aCol + 3][aRow] = na.w;
            *(float4*)&Bs[buf ^ 1][bRow][bCol] = nb;
            __syncthreads();
            buf ^= 1;
        }
    }

    // epilogue
#pragma unroll
    for (int i = 0; i < 8; ++i) {
        const int lr = (i < 4) ? (tr * 4 + i) : (64 + tr * 4 + (i - 4));
        const int r  = by * BM + lr;
#pragma unroll
        for (int j = 0; j < 8; ++j) {
            const int lc = (j < 4) ? (tc * 4 + j) : (64 + tc * 4 + (j - 4));
            const int n  = bx * BN + lc;
            if (EPI == 0) {
                C[(size_t)r * Nn + n] = lrelu(acc[i][j] + bias[n]);
            } else {
                const float t  = acc[i][j] + bias[n];
                const float xa = Zin[(size_t)r * DDIM + n];
                const float xb = Zin[(size_t)r * DDIM + D2 + n];
                const float yb = xb + rintf(t);   // rint = half-to-even = jnp.round
                Zout[(size_t)r * DDIM + (D2 - 1 - n)]   = yb;
                Zout[(size_t)r * DDIM + (DDIM - 1 - n)] = xa;
            }
        }
    }
}

// ---------------------------------------------------------------------------
// Per-block deterministic partial sums of log_p over 8 rows each.
// ---------------------------------------------------------------------------
__global__ __launch_bounds__(256)
void logp_kernel(const float* __restrict__ Z,
                 const float* __restrict__ mean,
                 const float* __restrict__ logscale)
{
    __shared__ double sred[256];
    const int b   = blockIdx.x;        // 0..1023, 8 rows each
    const int tid = threadIdx.x;
    const size_t base = (size_t)b * 8 * DDIM;

    double s = 0.0;
    for (int idx = tid; idx < 8 * DDIM; idx += 256) {
        const int d = idx & (DDIM - 1);
        const float z  = Z[base + idx];
        const float sc = expf(logscale[d]);
        const float m  = mean[d];
        const float u  = (z + 0.5f - m) / sc;
        const float v  = (z - 0.5f - m) / sc;
        const float la = logsigf(u);
        const float lb = logsigf(v);
        const float lp = la + logf(1.0f - expf(lb - la) + 1e-8f);
        s += (double)lp;
    }
    sred[tid] = s;
    __syncthreads();
#pragma unroll
    for (int off = 128; off > 0; off >>= 1) {
        if (tid < off) sred[tid] += sred[tid + off];
        __syncthreads();
    }
    if (tid == 0) g_partial[b] = sred[0];
}

__global__ __launch_bounds__(256)
void finalize_kernel(float* __restrict__ out)
{
    __shared__ double sred[256];
    const int tid = threadIdx.x;
    double s = 0.0;
    for (int i = tid; i < 1024; i += 256) s += g_partial[i];
    sred[tid] = s;
    __syncthreads();
#pragma unroll
    for (int off = 128; off > 0; off >>= 1) {
        if (tid < off) sred[tid] += sred[tid + off];
        __syncthreads();
    }
    if (tid == 0) out[0] = (float)(-sred[0] / (double)BSZ);
}

// ---------------------------------------------------------------------------
extern "C" void kernel_launch(void* const* d_in, const int* in_sizes, int n_in,
                              void* d_out, int out_size)
{
    const float* x        = (const float*)d_in[0];
    const float* W1       = (const float*)d_in[1];
    const float* b1       = (const float*)d_in[2];
    const float* W2       = (const float*)d_in[3];
    const float* b2       = (const float*)d_in[4];
    const float* W3       = (const float*)d_in[5];
    const float* b3       = (const float*)d_in[6];
    const float* mean     = (const float*)d_in[7];
    const float* logscale = (const float*)d_in[8];

    float *h1, *h2, *z0, *z1;
    cudaGetSymbolAddress((void**)&h1, g_h1);
    cudaGetSymbolAddress((void**)&h2, g_h2);
    cudaGetSymbolAddress((void**)&z0, g_z0);
    cudaGetSymbolAddress((void**)&z1, g_z1);

    const dim3 block(256);
    const dim3 grid12(NH / 128, BSZ / 128);  // (16, 64)
    const dim3 grid3 (D2 / 128, BSZ / 128);  // (4, 64)

    for (int f = 0; f < FSTEPS; ++f) {
        const float* zin  = (f == 0) ? x : ((f & 1) ? z0 : z1);
        float*       zout = (f & 1) ? z1 : z0;

        const float* W1f = W1 + (size_t)f * D2 * NH;
        const float* b1f = b1 + (size_t)f * NH;
        const float* W2f = W2 + (size_t)f * NH * NH;
        const float* b2f = b2 + (size_t)f * NH;
        const float* W3f = W3 + (size_t)f * NH * D2;
        const float* b3f = b3 + (size_t)f * D2;

        // h1 = lrelu(xa @ W1 + b1)    xa = zin[:, :512] (row stride 1024)
        sgemm_kernel<0><<<grid12, block>>>(zin, DDIM, W1f, b1f, h1,
                                           nullptr, nullptr, NH, D2);
        // h2 = lrelu(h1 @ W2 + b2)
        sgemm_kernel<0><<<grid12, block>>>(h1, NH, W2f, b2f, h2,
                                           nullptr, nullptr, NH, NH);
        // t = h2 @ W3 + b3 ; coupling + reversal fused
        sgemm_kernel<1><<<grid3, block>>>(h2, NH, W3f, b3f, nullptr,
                                          zin, zout, D2, NH);
    }

    // after 8 steps final z is in z1
    logp_kernel<<<1024, block>>>(z1, mean, logscale);
    finalize_kernel<<<1, block>>>((float*)d_out);
}